// round 2
// baseline (speedup 1.0000x reference)
#include <cuda_runtime.h>
#include <cstdint>

#define Bsz   8
#define Lseq  2048
#define DM    128
#define DI    256
#define DS    48
#define NROWS (Bsz*Lseq)
#define XDBL  104

__device__ float g_xn  [(size_t)NROWS*DM];
__device__ float g_xz  [(size_t)NROWS*512];
__device__ float g_ut  [2ull*Bsz*DI*Lseq];
__device__ float g_xdbl[2ull*NROWS*XDBL];
__device__ float g_dtt [2ull*Bsz*DI*Lseq];
__device__ float g_y   [2ull*NROWS*DI];

__device__ __forceinline__ float siluf(float v) { return v / (1.f + __expf(-v)); }

// ---------------- 1. LayerNorm ----------------
__global__ void ln_kernel(const float* __restrict__ x, const float* __restrict__ w,
                          const float* __restrict__ b) {
    int row  = blockIdx.x * 8 + (threadIdx.x >> 5);
    int lane = threadIdx.x & 31;
    float4 v = *(const float4*)(x + (size_t)row*DM + lane*4);
    float s  = v.x + v.y + v.z + v.w;
    float ss = v.x*v.x + v.y*v.y + v.z*v.z + v.w*v.w;
    #pragma unroll
    for (int o = 16; o; o >>= 1) {
        s  += __shfl_xor_sync(0xffffffffu, s,  o);
        ss += __shfl_xor_sync(0xffffffffu, ss, o);
    }
    float mu  = s * (1.f/128.f);
    float rs  = rsqrtf(ss * (1.f/128.f) - mu*mu + 1e-5f);
    float4 wv = *(const float4*)(w + lane*4);
    float4 bv = *(const float4*)(b + lane*4);
    float4 o4;
    o4.x = (v.x-mu)*rs*wv.x + bv.x;
    o4.y = (v.y-mu)*rs*wv.y + bv.y;
    o4.z = (v.z-mu)*rs*wv.z + bv.z;
    o4.w = (v.w-mu)*rs*wv.w + bv.w;
    *(float4*)(g_xn + (size_t)row*DM + lane*4) = o4;
}

// ---------------- 2. in_proj GEMM: M=16384,N=512,K=128 ----------------
__global__ void gemm_inproj(const float* __restrict__ W) {
    __shared__ __align__(16) float As[16][68];
    __shared__ __align__(16) float Bs[16][68];
    int tid  = threadIdx.x;
    int bm0  = blockIdx.y * 64, bn0 = blockIdx.x * 64;
    int arow = tid >> 2, acol = (tid & 3) * 4;
    int ty   = tid >> 4, tx = tid & 15;
    float acc[4][4] = {};
    for (int k0 = 0; k0 < 128; k0 += 16) {
        float4 av = *(const float4*)(g_xn + (size_t)(bm0+arow)*DM + k0 + acol);
        As[acol+0][arow]=av.x; As[acol+1][arow]=av.y; As[acol+2][arow]=av.z; As[acol+3][arow]=av.w;
        float4 wv = *(const float4*)(W + (size_t)(bn0+arow)*DM + k0 + acol);
        Bs[acol+0][arow]=wv.x; Bs[acol+1][arow]=wv.y; Bs[acol+2][arow]=wv.z; Bs[acol+3][arow]=wv.w;
        __syncthreads();
        #pragma unroll
        for (int kk = 0; kk < 16; kk++) {
            float4 a = *(float4*)&As[kk][ty*4];
            float4 b = *(float4*)&Bs[kk][tx*4];
            float av4[4]={a.x,a.y,a.z,a.w}, bv4[4]={b.x,b.y,b.z,b.w};
            #pragma unroll
            for (int i=0;i<4;i++)
                #pragma unroll
                for (int j=0;j<4;j++) acc[i][j] += av4[i]*bv4[j];
        }
        __syncthreads();
    }
    #pragma unroll
    for (int i=0;i<4;i++) {
        float4 o4 = make_float4(acc[i][0],acc[i][1],acc[i][2],acc[i][3]);
        *(float4*)(g_xz + (size_t)(bm0+ty*4+i)*512 + bn0 + tx*4) = o4;
    }
}

// ---------------- 3. conv + silu (both dirs), u transposed ----------------
__global__ void conv_kernel(const float* __restrict__ cwF, const float* __restrict__ cbF,
                            const float* __restrict__ cwB, const float* __restrict__ cbB) {
    int c  = blockIdx.x * 128 + threadIdx.x;
    int t0 = blockIdx.y * 128;
    int bz = blockIdx.z; int b = bz >> 1; int br = bz & 1;
    const float* w4 = (br ? cwB : cwF) + c*4;
    float w0=w4[0], w1=w4[1], w2=w4[2], w3=w4[3];
    float bias = (br ? cbB : cbF)[c];
    const float* xzb = g_xz + (size_t)b*Lseq*512 + c;
    float* uo = g_ut + (((size_t)br*Bsz + b)*DI + c)*Lseq + t0;
    float r0, r1, r2;
    if (!br) {
        r0 = (t0-3 >= 0) ? xzb[(size_t)(t0-3)*512] : 0.f;
        r1 = (t0-2 >= 0) ? xzb[(size_t)(t0-2)*512] : 0.f;
        r2 = (t0-1 >= 0) ? xzb[(size_t)(t0-1)*512] : 0.f;
        for (int i = 0; i < 128; i++) {
            float r3 = xzb[(size_t)(t0+i)*512];
            uo[i] = siluf(r0*w0 + r1*w1 + r2*w2 + r3*w3 + bias);
            r0 = r1; r1 = r2; r2 = r3;
        }
    } else {
        r0 = (t0 >= 3) ? xzb[(size_t)(Lseq+2-t0)*512] : 0.f;
        r1 = (t0 >= 2) ? xzb[(size_t)(Lseq+1-t0)*512] : 0.f;
        r2 = (t0 >= 1) ? xzb[(size_t)(Lseq  -t0)*512] : 0.f;
        for (int i = 0; i < 128; i++) {
            float r3 = xzb[(size_t)(Lseq-1-(t0+i))*512];
            uo[i] = siluf(r0*w0 + r1*w1 + r2*w2 + r3*w3 + bias);
            r0 = r1; r1 = r2; r2 = r3;
        }
    }
}

// ---------------- 4. x_proj GEMM: M=16384,N=104,K=256 (A is K-major u) ----------------
__global__ void gemm_xproj(const float* __restrict__ WF, const float* __restrict__ WB) {
    __shared__ __align__(16) float As[16][68];
    __shared__ __align__(16) float Bs[16][68];
    int br = blockIdx.z;
    const float* W = br ? WB : WF;
    int tid  = threadIdx.x;
    int bn0  = blockIdx.x * 64, bm0 = blockIdx.y * 64;
    int b    = bm0 >> 11, l0 = bm0 & 2047;
    int krow = tid >> 4, mcol = (tid & 15) * 4;
    int wrow = tid >> 2, wcol = (tid & 3) * 4;
    int ty   = tid >> 4, tx = tid & 15;
    const float* Abase = g_ut + (((size_t)br*Bsz + b)*DI) * Lseq + l0;
    float acc[4][4] = {};
    for (int k0 = 0; k0 < 256; k0 += 16) {
        *(float4*)&As[krow][mcol] = *(const float4*)(Abase + (size_t)(k0+krow)*Lseq + mcol);
        int n = bn0 + wrow;
        float4 bv = make_float4(0.f,0.f,0.f,0.f);
        if (n < XDBL) bv = *(const float4*)(W + (size_t)n*256 + k0 + wcol);
        Bs[wcol+0][wrow]=bv.x; Bs[wcol+1][wrow]=bv.y; Bs[wcol+2][wrow]=bv.z; Bs[wcol+3][wrow]=bv.w;
        __syncthreads();
        #pragma unroll
        for (int kk = 0; kk < 16; kk++) {
            float4 a = *(float4*)&As[kk][ty*4];
            float4 b4 = *(float4*)&Bs[kk][tx*4];
            float av4[4]={a.x,a.y,a.z,a.w}, bv4[4]={b4.x,b4.y,b4.z,b4.w};
            #pragma unroll
            for (int i=0;i<4;i++)
                #pragma unroll
                for (int j=0;j<4;j++) acc[i][j] += av4[i]*bv4[j];
        }
        __syncthreads();
    }
    float* C = g_xdbl + (size_t)br*NROWS*XDBL;
    #pragma unroll
    for (int i=0;i<4;i++)
        #pragma unroll
        for (int j=0;j<4;j++) {
            int n = bn0 + tx*4 + j;
            if (n < XDBL) C[(size_t)(bm0+ty*4+i)*XDBL + n] = acc[i][j];
        }
}

// ---------------- 5. dt_proj + softplus, transposed out ----------------
__global__ void dtproj_kernel(const float* __restrict__ dwF, const float* __restrict__ dbF,
                              const float* __restrict__ dwB, const float* __restrict__ dbB) {
    int w = threadIdx.x >> 5, lane = threadIdx.x & 31;
    int l  = blockIdx.x * 32 + lane;
    int d  = blockIdx.y * 8 + w;
    int br = blockIdx.z >> 3, b = blockIdx.z & 7;
    const float* dw = (br ? dwB : dwF) + d*8;
    float acc = (br ? dbB : dbF)[d];
    const float* xr = g_xdbl + (size_t)br*NROWS*XDBL + ((size_t)b*Lseq + l)*XDBL;
    #pragma unroll
    for (int r = 0; r < 8; r++) acc += xr[r] * dw[r];
    float sp = (acc > 15.f) ? acc : log1pf(__expf(acc));
    g_dtt[(((size_t)br*Bsz + b)*DI + d)*Lseq + l] = sp;
}

// ---------------- 6. selective scan ----------------
__global__ void scan_kernel(const float* __restrict__ AlogF, const float* __restrict__ DpF,
                            const float* __restrict__ AlogB, const float* __restrict__ DpB) {
    int warp = threadIdx.x >> 5, lane = threadIdx.x & 31;
    int dp = blockIdx.x * 2 + warp;
    int b  = blockIdx.y, br = blockIdx.z;
    int half = lane >> 4, sub = lane & 15;
    int d = dp * 2 + half;
    const float* Alog = br ? AlogB : AlogF;
    const float* Dpv  = br ? DpB  : DpF;
    float A0 = -__expf(Alog[d*DS + sub     ]);
    float A1 = -__expf(Alog[d*DS + sub + 16]);
    float A2 = -__expf(Alog[d*DS + sub + 32]);
    float Dpd = Dpv[d];
    const float* dtp = g_dtt + (((size_t)br*Bsz + b)*DI + d)*Lseq;
    const float* up  = g_ut  + (((size_t)br*Bsz + b)*DI + d)*Lseq;
    const float* xd  = g_xdbl + ((size_t)br*NROWS + (size_t)b*Lseq)*XDBL;
    float* yo = g_y + ((size_t)br*NROWS + (size_t)b*Lseq)*DI + d;

    float h0 = 0.f, h1 = 0.f, h2 = 0.f;
    float4 dt4 = *(const float4*)dtp;
    float4 u4  = *(const float4*)up;
    float Bv[4][3], Cv[4][3];
    #pragma unroll
    for (int i = 0; i < 4; i++) {
        const float* xr = xd + (size_t)i*XDBL;
        Bv[i][0]=xr[ 8+sub]; Bv[i][1]=xr[24+sub]; Bv[i][2]=xr[40+sub];
        Cv[i][0]=xr[56+sub]; Cv[i][1]=xr[72+sub]; Cv[i][2]=xr[88+sub];
    }
    for (int t0 = 0; t0 < Lseq; t0 += 4) {
        int tn = (t0 + 4 < Lseq) ? (t0 + 4) : t0;
        float4 dt4n = *(const float4*)(dtp + tn);
        float4 u4n  = *(const float4*)(up + tn);
        float Bn[4][3], Cn[4][3];
        #pragma unroll
        for (int i = 0; i < 4; i++) {
            const float* xr = xd + (size_t)(tn + i)*XDBL;
            Bn[i][0]=xr[ 8+sub]; Bn[i][1]=xr[24+sub]; Bn[i][2]=xr[40+sub];
            Cn[i][0]=xr[56+sub]; Cn[i][1]=xr[72+sub]; Cn[i][2]=xr[88+sub];
        }
        float dts[4] = {dt4.x, dt4.y, dt4.z, dt4.w};
        float us [4] = {u4.x,  u4.y,  u4.z,  u4.w};
        #pragma unroll
        for (int i = 0; i < 4; i++) {
            float dtv = dts[i], uv = us[i];
            float du = dtv * uv;
            h0 = __expf(dtv*A0)*h0 + du*Bv[i][0];
            h1 = __expf(dtv*A1)*h1 + du*Bv[i][1];
            h2 = __expf(dtv*A2)*h2 + du*Bv[i][2];
            float p = h0*Cv[i][0] + h1*Cv[i][1] + h2*Cv[i][2];
            p += __shfl_xor_sync(0xffffffffu, p, 8);
            p += __shfl_xor_sync(0xffffffffu, p, 4);
            p += __shfl_xor_sync(0xffffffffu, p, 2);
            p += __shfl_xor_sync(0xffffffffu, p, 1);
            if (sub == 0) {
                int t = t0 + i;
                int row = br ? (Lseq - 1 - t) : t;
                yo[(size_t)row*DI] = p + uv * Dpd;
            }
        }
        dt4 = dt4n; u4 = u4n;
        #pragma unroll
        for (int i = 0; i < 4; i++) {
            Bv[i][0]=Bn[i][0]; Bv[i][1]=Bn[i][1]; Bv[i][2]=Bn[i][2];
            Cv[i][0]=Cn[i][0]; Cv[i][1]=Cn[i][1]; Cv[i][2]=Cn[i][2];
        }
    }
}

// ---------------- 7. out_proj GEMM fused gate+residual: M=16384,N=128,K=256 ----------------
__global__ void gemm_out(const float* __restrict__ W, const float* __restrict__ x,
                         float* __restrict__ out) {
    __shared__ __align__(16) float As[16][68];
    __shared__ __align__(16) float Bs[16][68];
    int tid  = threadIdx.x;
    int bm0  = blockIdx.y * 64, bn0 = blockIdx.x * 64;
    int arow = tid >> 2, acol = (tid & 3) * 4;
    int ty   = tid >> 4, tx = tid & 15;
    float acc[4][4] = {};
    for (int k0 = 0; k0 < 256; k0 += 16) {
        size_t m = (size_t)(bm0 + arow);
        size_t idx = m*DI + k0 + acol;
        float4 yf = *(const float4*)(g_y + idx);
        float4 yb = *(const float4*)(g_y + (size_t)NROWS*DI + idx);
        float4 zz = *(const float4*)(g_xz + m*512 + 256 + k0 + acol);
        float4 av;
        av.x = (yf.x + yb.x) * siluf(zz.x);
        av.y = (yf.y + yb.y) * siluf(zz.y);
        av.z = (yf.z + yb.z) * siluf(zz.z);
        av.w = (yf.w + yb.w) * siluf(zz.w);
        As[acol+0][arow]=av.x; As[acol+1][arow]=av.y; As[acol+2][arow]=av.z; As[acol+3][arow]=av.w;
        float4 wv = *(const float4*)(W + (size_t)(bn0+arow)*DI + k0 + acol);
        Bs[acol+0][arow]=wv.x; Bs[acol+1][arow]=wv.y; Bs[acol+2][arow]=wv.z; Bs[acol+3][arow]=wv.w;
        __syncthreads();
        #pragma unroll
        for (int kk = 0; kk < 16; kk++) {
            float4 a = *(float4*)&As[kk][ty*4];
            float4 b = *(float4*)&Bs[kk][tx*4];
            float av4[4]={a.x,a.y,a.z,a.w}, bv4[4]={b.x,b.y,b.z,b.w};
            #pragma unroll
            for (int i=0;i<4;i++)
                #pragma unroll
                for (int j=0;j<4;j++) acc[i][j] += av4[i]*bv4[j];
        }
        __syncthreads();
    }
    #pragma unroll
    for (int i = 0; i < 4; i++) {
        size_t m = (size_t)(bm0 + ty*4 + i);
        float4 r = *(const float4*)(x + m*DM + bn0 + tx*4);
        float4 o4 = make_float4(acc[i][0]+r.x, acc[i][1]+r.y, acc[i][2]+r.z, acc[i][3]+r.w);
        *(float4*)(out + m*DM + bn0 + tx*4) = o4;
    }
}

extern "C" void kernel_launch(void* const* d_in, const int* in_sizes, int n_in,
                              void* d_out, int out_size) {
    const float* x        = (const float*)d_in[0];
    const float* ln_w     = (const float*)d_in[1];
    const float* ln_b     = (const float*)d_in[2];
    const float* in_w     = (const float*)d_in[3];
    const float* out_w    = (const float*)d_in[4];
    const float* conv_w   = (const float*)d_in[5];
    const float* conv_b   = (const float*)d_in[6];
    const float* xproj_w  = (const float*)d_in[7];
    const float* dt_w     = (const float*)d_in[8];
    const float* dt_b     = (const float*)d_in[9];
    const float* A_log    = (const float*)d_in[10];
    const float* Dp       = (const float*)d_in[11];
    const float* conv_wb  = (const float*)d_in[12];
    const float* conv_bb  = (const float*)d_in[13];
    const float* xproj_wb = (const float*)d_in[14];
    const float* dt_wb    = (const float*)d_in[15];
    const float* dt_bb    = (const float*)d_in[16];
    const float* A_logb   = (const float*)d_in[17];
    const float* Dpb      = (const float*)d_in[18];
    float* out = (float*)d_out;

    ln_kernel<<<NROWS/8, 256>>>(x, ln_w, ln_b);
    gemm_inproj<<<dim3(8, NROWS/64), 256>>>(in_w);
    conv_kernel<<<dim3(2, 16, 16), 128>>>(conv_w, conv_b, conv_wb, conv_bb);
    gemm_xproj<<<dim3(2, NROWS/64, 2), 256>>>(xproj_w, xproj_wb);
    dtproj_kernel<<<dim3(64, 32, 16), 256>>>(dt_w, dt_b, dt_wb, dt_bb);
    scan_kernel<<<dim3(64, 8, 2), 64>>>(A_log, Dp, A_logb, Dpb);
    gemm_out<<<dim3(2, NROWS/64), 256>>>(out_w, x, out);
}

// round 3
// speedup vs baseline: 1.2139x; 1.2139x over previous
#include <cuda_runtime.h>
#include <cstdint>

#define Bsz   8
#define Lseq  2048
#define DM    128
#define DI    256
#define DS    48
#define NROWS (Bsz*Lseq)

__device__ float g_xn   [(size_t)NROWS*DM];
__device__ float g_xz   [(size_t)NROWS*512];
__device__ float g_ut   [2ull*Bsz*DI*Lseq];
__device__ float g_dtraw[2ull*NROWS*8];
__device__ float g_bc   [2ull*NROWS*96];
__device__ float g_dtt  [2ull*Bsz*DI*Lseq];
__device__ float g_y    [2ull*NROWS*DI];

__device__ __forceinline__ float siluf(float v) { return v / (1.f + __expf(-v)); }
__device__ __forceinline__ float ex2f(float x) {
    float r; asm("ex2.approx.ftz.f32 %0, %1;" : "=f"(r) : "f"(x)); return r;
}

// ---------------- 1. LayerNorm ----------------
__global__ void ln_kernel(const float* __restrict__ x, const float* __restrict__ w,
                          const float* __restrict__ b) {
    int row  = blockIdx.x * 8 + (threadIdx.x >> 5);
    int lane = threadIdx.x & 31;
    float4 v = *(const float4*)(x + (size_t)row*DM + lane*4);
    float s  = v.x + v.y + v.z + v.w;
    float ss = v.x*v.x + v.y*v.y + v.z*v.z + v.w*v.w;
    #pragma unroll
    for (int o = 16; o; o >>= 1) {
        s  += __shfl_xor_sync(0xffffffffu, s,  o);
        ss += __shfl_xor_sync(0xffffffffu, ss, o);
    }
    float mu  = s * (1.f/128.f);
    float rs  = rsqrtf(ss * (1.f/128.f) - mu*mu + 1e-5f);
    float4 wv = *(const float4*)(w + lane*4);
    float4 bv = *(const float4*)(b + lane*4);
    float4 o4;
    o4.x = (v.x-mu)*rs*wv.x + bv.x;
    o4.y = (v.y-mu)*rs*wv.y + bv.y;
    o4.z = (v.z-mu)*rs*wv.z + bv.z;
    o4.w = (v.w-mu)*rs*wv.w + bv.w;
    *(float4*)(g_xn + (size_t)row*DM + lane*4) = o4;
}

// ---------------- 2. in_proj GEMM: M=16384,N=512,K=128, 128x64 tiles ----------------
__global__ void gemm_inproj(const float* __restrict__ W) {
    __shared__ __align__(16) float As[16][132];
    __shared__ __align__(16) float Bs[16][68];
    int tid = threadIdx.x;
    int bm0 = blockIdx.y * 128, bn0 = blockIdx.x * 64;
    int ar = tid >> 1, ac = (tid & 1) * 8;
    int brw = tid >> 2, bc = (tid & 3) * 4;
    int ty = tid >> 4, tx = tid & 15;
    float acc[8][4] = {};
    for (int k0 = 0; k0 < 128; k0 += 16) {
        float4 a0 = *(const float4*)(g_xn + (size_t)(bm0+ar)*DM + k0 + ac);
        float4 a1 = *(const float4*)(g_xn + (size_t)(bm0+ar)*DM + k0 + ac + 4);
        As[ac+0][ar]=a0.x; As[ac+1][ar]=a0.y; As[ac+2][ar]=a0.z; As[ac+3][ar]=a0.w;
        As[ac+4][ar]=a1.x; As[ac+5][ar]=a1.y; As[ac+6][ar]=a1.z; As[ac+7][ar]=a1.w;
        float4 wv = *(const float4*)(W + (size_t)(bn0+brw)*DM + k0 + bc);
        Bs[bc+0][brw]=wv.x; Bs[bc+1][brw]=wv.y; Bs[bc+2][brw]=wv.z; Bs[bc+3][brw]=wv.w;
        __syncthreads();
        #pragma unroll
        for (int kk = 0; kk < 16; kk++) {
            float4 x0 = *(float4*)&As[kk][ty*8];
            float4 x1 = *(float4*)&As[kk][ty*8+4];
            float4 bb = *(float4*)&Bs[kk][tx*4];
            float am[8] = {x0.x,x0.y,x0.z,x0.w,x1.x,x1.y,x1.z,x1.w};
            float bn[4] = {bb.x,bb.y,bb.z,bb.w};
            #pragma unroll
            for (int i=0;i<8;i++)
                #pragma unroll
                for (int j=0;j<4;j++) acc[i][j] += am[i]*bn[j];
        }
        __syncthreads();
    }
    #pragma unroll
    for (int i=0;i<8;i++) {
        float4 o4 = make_float4(acc[i][0],acc[i][1],acc[i][2],acc[i][3]);
        *(float4*)(g_xz + (size_t)(bm0+ty*8+i)*512 + bn0 + tx*4) = o4;
    }
}

// ---------------- 3. conv + silu (both dirs), u transposed ----------------
__global__ void conv_kernel(const float* __restrict__ cwF, const float* __restrict__ cbF,
                            const float* __restrict__ cwB, const float* __restrict__ cbB) {
    int c  = blockIdx.x * 128 + threadIdx.x;
    int t0 = blockIdx.y * 128;
    int bz = blockIdx.z; int b = bz >> 1; int br = bz & 1;
    const float* w4 = (br ? cwB : cwF) + c*4;
    float w0=w4[0], w1=w4[1], w2=w4[2], w3=w4[3];
    float bias = (br ? cbB : cbF)[c];
    const float* xzb = g_xz + (size_t)b*Lseq*512 + c;
    float* uo = g_ut + (((size_t)br*Bsz + b)*DI + c)*Lseq + t0;
    float r0, r1, r2;
    if (!br) {
        r0 = (t0-3 >= 0) ? xzb[(size_t)(t0-3)*512] : 0.f;
        r1 = (t0-2 >= 0) ? xzb[(size_t)(t0-2)*512] : 0.f;
        r2 = (t0-1 >= 0) ? xzb[(size_t)(t0-1)*512] : 0.f;
        for (int i = 0; i < 128; i++) {
            float r3 = xzb[(size_t)(t0+i)*512];
            uo[i] = siluf(r0*w0 + r1*w1 + r2*w2 + r3*w3 + bias);
            r0 = r1; r1 = r2; r2 = r3;
        }
    } else {
        r0 = (t0 >= 3) ? xzb[(size_t)(Lseq+2-t0)*512] : 0.f;
        r1 = (t0 >= 2) ? xzb[(size_t)(Lseq+1-t0)*512] : 0.f;
        r2 = (t0 >= 1) ? xzb[(size_t)(Lseq  -t0)*512] : 0.f;
        for (int i = 0; i < 128; i++) {
            float r3 = xzb[(size_t)(Lseq-1-(t0+i))*512];
            uo[i] = siluf(r0*w0 + r1*w1 + r2*w2 + r3*w3 + bias);
            r0 = r1; r1 = r2; r2 = r3;
        }
    }
}

// ---------------- 4. x_proj GEMM: M=16384,N=104,K=256 (A K-major), split store ----------------
__global__ void gemm_xproj(const float* __restrict__ WF, const float* __restrict__ WB) {
    __shared__ __align__(16) float As[16][132];
    __shared__ __align__(16) float Bs[16][68];
    int brz = blockIdx.z;
    const float* W = brz ? WB : WF;
    int tid = threadIdx.x;
    int bn0 = blockIdx.x * 64, bm0 = blockIdx.y * 128;
    int b = bm0 >> 11, l0 = bm0 & 2047;
    int kr = tid >> 4, m4 = (tid & 15) * 4;
    int wr = tid >> 2, wc = (tid & 3) * 4;
    int ty = tid >> 4, tx = tid & 15;
    const float* Abase = g_ut + (((size_t)brz*Bsz + b)*DI) * Lseq + l0;
    float acc[8][4] = {};
    for (int k0 = 0; k0 < 256; k0 += 16) {
        *(float4*)&As[kr][m4]    = *(const float4*)(Abase + (size_t)(k0+kr)*Lseq + m4);
        *(float4*)&As[kr][m4+64] = *(const float4*)(Abase + (size_t)(k0+kr)*Lseq + m4 + 64);
        int n = bn0 + wr;
        float4 bv = make_float4(0.f,0.f,0.f,0.f);
        if (n < 104) bv = *(const float4*)(W + (size_t)n*256 + k0 + wc);
        Bs[wc+0][wr]=bv.x; Bs[wc+1][wr]=bv.y; Bs[wc+2][wr]=bv.z; Bs[wc+3][wr]=bv.w;
        __syncthreads();
        #pragma unroll
        for (int kk = 0; kk < 16; kk++) {
            float4 x0 = *(float4*)&As[kk][ty*8];
            float4 x1 = *(float4*)&As[kk][ty*8+4];
            float4 bb = *(float4*)&Bs[kk][tx*4];
            float am[8] = {x0.x,x0.y,x0.z,x0.w,x1.x,x1.y,x1.z,x1.w};
            float bn[4] = {bb.x,bb.y,bb.z,bb.w};
            #pragma unroll
            for (int i=0;i<8;i++)
                #pragma unroll
                for (int j=0;j<4;j++) acc[i][j] += am[i]*bn[j];
        }
        __syncthreads();
    }
    float* draw = g_dtraw + (size_t)brz*NROWS*8;
    float* bcp  = g_bc    + (size_t)brz*NROWS*96;
    #pragma unroll
    for (int i=0;i<8;i++) {
        size_t row = (size_t)(bm0 + ty*8 + i);
        #pragma unroll
        for (int j=0;j<4;j++) {
            int n = bn0 + tx*4 + j;
            if (n < 8)        draw[row*8 + n]      = acc[i][j];
            else if (n < 104) bcp [row*96 + n - 8] = acc[i][j];
        }
    }
}

// ---------------- 5. dt_proj + softplus (coalesced) ----------------
__global__ void dtproj_kernel(const float* __restrict__ dwF, const float* __restrict__ dbF,
                              const float* __restrict__ dwB, const float* __restrict__ dbB) {
    __shared__ float ws[64][9];
    int tid = threadIdx.x;
    int l  = blockIdx.x * 256 + tid;
    int d0 = blockIdx.y * 64;
    int br = blockIdx.z >> 3, b = blockIdx.z & 7;
    const float* dw = br ? dwB : dwF;
    const float* db = br ? dbB : dbF;
    for (int i = tid; i < 512; i += 256) ws[i>>3][i&7] = dw[(d0 + (i>>3))*8 + (i&7)];
    if (tid < 64) ws[tid][8] = db[d0 + tid];
    __syncthreads();
    const float* xr = g_dtraw + (size_t)br*NROWS*8 + ((size_t)b*Lseq + l)*8;
    float4 x0 = *(const float4*)xr;
    float4 x1 = *(const float4*)(xr + 4);
    float xv[8] = {x0.x,x0.y,x0.z,x0.w,x1.x,x1.y,x1.z,x1.w};
    float* outp = g_dtt + (((size_t)br*Bsz + b)*DI + d0)*Lseq + l;
    for (int d = 0; d < 64; d++) {
        float acc = ws[d][8];
        #pragma unroll
        for (int r = 0; r < 8; r++) acc += xv[r] * ws[d][r];
        float sp = (acc > 15.f) ? acc : log1pf(__expf(acc));
        outp[(size_t)d*Lseq] = sp;
    }
}

// ---------------- 6. selective scan ----------------
__global__ void scan_kernel(const float* __restrict__ AlogF, const float* __restrict__ DpF,
                            const float* __restrict__ AlogB, const float* __restrict__ DpB) {
    int warp = threadIdx.x >> 5, lane = threadIdx.x & 31;
    int dp = blockIdx.x * 2 + warp;
    int b  = blockIdx.y, br = blockIdx.z;
    int half = lane >> 4, sub = lane & 15;
    int d = dp * 2 + half;
    const float* Alog = br ? AlogB : AlogF;
    const float* Dpv  = br ? DpB  : DpF;
    const float L2E = 1.44269504f;
    float A0 = -__expf(Alog[d*DS + sub     ]) * L2E;
    float A1 = -__expf(Alog[d*DS + sub + 16]) * L2E;
    float A2 = -__expf(Alog[d*DS + sub + 32]) * L2E;
    float Dpd = Dpv[d];
    const float* dtp = g_dtt + (((size_t)br*Bsz + b)*DI + d)*Lseq;
    const float* up  = g_ut  + (((size_t)br*Bsz + b)*DI + d)*Lseq;
    const float* xd  = g_bc + ((size_t)br*NROWS + (size_t)b*Lseq)*96;
    float* yo = g_y + ((size_t)br*NROWS + (size_t)b*Lseq)*DI + d;

    float h0 = 0.f, h1 = 0.f, h2 = 0.f;
    float4 dt4 = *(const float4*)dtp;
    float4 u4  = *(const float4*)up;
    float Bv[4][3], Cv[4][3];
    #pragma unroll
    for (int i = 0; i < 4; i++) {
        const float* xr = xd + (size_t)i*96;
        Bv[i][0]=xr[sub];    Bv[i][1]=xr[16+sub]; Bv[i][2]=xr[32+sub];
        Cv[i][0]=xr[48+sub]; Cv[i][1]=xr[64+sub]; Cv[i][2]=xr[80+sub];
    }
    for (int t0 = 0; t0 < Lseq; t0 += 4) {
        int tn = (t0 + 4 < Lseq) ? (t0 + 4) : t0;
        float4 dt4n = *(const float4*)(dtp + tn);
        float4 u4n  = *(const float4*)(up + tn);
        float Bn[4][3], Cn[4][3];
        #pragma unroll
        for (int i = 0; i < 4; i++) {
            const float* xr = xd + (size_t)(tn + i)*96;
            Bn[i][0]=xr[sub];    Bn[i][1]=xr[16+sub]; Bn[i][2]=xr[32+sub];
            Cn[i][0]=xr[48+sub]; Cn[i][1]=xr[64+sub]; Cn[i][2]=xr[80+sub];
        }
        float dts[4] = {dt4.x, dt4.y, dt4.z, dt4.w};
        float us [4] = {u4.x,  u4.y,  u4.z,  u4.w};
        #pragma unroll
        for (int i = 0; i < 4; i++) {
            float dtv = dts[i], uv = us[i];
            float du = dtv * uv;
            h0 = ex2f(dtv*A0)*h0 + du*Bv[i][0];
            h1 = ex2f(dtv*A1)*h1 + du*Bv[i][1];
            h2 = ex2f(dtv*A2)*h2 + du*Bv[i][2];
            float p = h0*Cv[i][0] + h1*Cv[i][1] + h2*Cv[i][2];
            p += __shfl_xor_sync(0xffffffffu, p, 8);
            p += __shfl_xor_sync(0xffffffffu, p, 4);
            p += __shfl_xor_sync(0xffffffffu, p, 2);
            p += __shfl_xor_sync(0xffffffffu, p, 1);
            if (sub == 0) {
                int t = t0 + i;
                int row = br ? (Lseq - 1 - t) : t;
                yo[(size_t)row*DI] = p + uv * Dpd;
            }
        }
        dt4 = dt4n; u4 = u4n;
        #pragma unroll
        for (int i = 0; i < 4; i++) {
            Bv[i][0]=Bn[i][0]; Bv[i][1]=Bn[i][1]; Bv[i][2]=Bn[i][2];
            Cv[i][0]=Cn[i][0]; Cv[i][1]=Cn[i][1]; Cv[i][2]=Cn[i][2];
        }
    }
}

// ---------------- 7. out_proj GEMM fused gate+residual: M=16384,N=128,K=256 ----------------
__global__ void gemm_out(const float* __restrict__ W, const float* __restrict__ x,
                         float* __restrict__ out) {
    __shared__ __align__(16) float As[16][132];
    __shared__ __align__(16) float Bs[16][68];
    int tid = threadIdx.x;
    int bm0 = blockIdx.y * 128, bn0 = blockIdx.x * 64;
    int ar = tid >> 1, ac = (tid & 1) * 8;
    int brw = tid >> 2, bc = (tid & 3) * 4;
    int ty = tid >> 4, tx = tid & 15;
    float acc[8][4] = {};
    for (int k0 = 0; k0 < 256; k0 += 16) {
        size_t m = (size_t)(bm0 + ar);
        #pragma unroll
        for (int h = 0; h < 2; h++) {
            size_t idx = m*DI + k0 + ac + h*4;
            float4 yf = *(const float4*)(g_y + idx);
            float4 yb = *(const float4*)(g_y + (size_t)NROWS*DI + idx);
            float4 zz = *(const float4*)(g_xz + m*512 + 256 + k0 + ac + h*4);
            As[ac+h*4+0][ar] = (yf.x + yb.x) * siluf(zz.x);
            As[ac+h*4+1][ar] = (yf.y + yb.y) * siluf(zz.y);
            As[ac+h*4+2][ar] = (yf.z + yb.z) * siluf(zz.z);
            As[ac+h*4+3][ar] = (yf.w + yb.w) * siluf(zz.w);
        }
        float4 wv = *(const float4*)(W + (size_t)(bn0+brw)*DI + k0 + bc);
        Bs[bc+0][brw]=wv.x; Bs[bc+1][brw]=wv.y; Bs[bc+2][brw]=wv.z; Bs[bc+3][brw]=wv.w;
        __syncthreads();
        #pragma unroll
        for (int kk = 0; kk < 16; kk++) {
            float4 x0 = *(float4*)&As[kk][ty*8];
            float4 x1 = *(float4*)&As[kk][ty*8+4];
            float4 bb = *(float4*)&Bs[kk][tx*4];
            float am[8] = {x0.x,x0.y,x0.z,x0.w,x1.x,x1.y,x1.z,x1.w};
            float bn[4] = {bb.x,bb.y,bb.z,bb.w};
            #pragma unroll
            for (int i=0;i<8;i++)
                #pragma unroll
                for (int j=0;j<4;j++) acc[i][j] += am[i]*bn[j];
        }
        __syncthreads();
    }
    #pragma unroll
    for (int i = 0; i < 8; i++) {
        size_t m = (size_t)(bm0 + ty*8 + i);
        float4 r = *(const float4*)(x + m*DM + bn0 + tx*4);
        float4 o4 = make_float4(acc[i][0]+r.x, acc[i][1]+r.y, acc[i][2]+r.z, acc[i][3]+r.w);
        *(float4*)(out + m*DM + bn0 + tx*4) = o4;
    }
}

extern "C" void kernel_launch(void* const* d_in, const int* in_sizes, int n_in,
                              void* d_out, int out_size) {
    const float* x        = (const float*)d_in[0];
    const float* ln_w     = (const float*)d_in[1];
    const float* ln_b     = (const float*)d_in[2];
    const float* in_w     = (const float*)d_in[3];
    const float* out_w    = (const float*)d_in[4];
    const float* conv_w   = (const float*)d_in[5];
    const float* conv_b   = (const float*)d_in[6];
    const float* xproj_w  = (const float*)d_in[7];
    const float* dt_w     = (const float*)d_in[8];
    const float* dt_b     = (const float*)d_in[9];
    const float* A_log    = (const float*)d_in[10];
    const float* Dp       = (const float*)d_in[11];
    const float* conv_wb  = (const float*)d_in[12];
    const float* conv_bb  = (const float*)d_in[13];
    const float* xproj_wb = (const float*)d_in[14];
    const float* dt_wb    = (const float*)d_in[15];
    const float* dt_bb    = (const float*)d_in[16];
    const float* A_logb   = (const float*)d_in[17];
    const float* Dpb      = (const float*)d_in[18];
    float* out = (float*)d_out;

    ln_kernel<<<NROWS/8, 256>>>(x, ln_w, ln_b);
    gemm_inproj<<<dim3(8, 128), 256>>>(in_w);
    conv_kernel<<<dim3(2, 16, 16), 128>>>(conv_w, conv_b, conv_wb, conv_bb);
    gemm_xproj<<<dim3(2, 128, 2), 256>>>(xproj_w, xproj_wb);
    dtproj_kernel<<<dim3(8, 4, 16), 256>>>(dt_w, dt_b, dt_wb, dt_bb);
    scan_kernel<<<dim3(64, 8, 2), 64>>>(A_log, Dp, A_logb, Dpb);
    gemm_out<<<dim3(2, 128), 256>>>(out_w, x, out);
}

// round 4
// speedup vs baseline: 1.2337x; 1.0163x over previous
#include <cuda_runtime.h>
#include <cstdint>

#define Bsz   8
#define Lseq  2048
#define DM    128
#define DI    256
#define DS    48
#define NROWS (Bsz*Lseq)

__device__ float g_xn   [(size_t)NROWS*DM];
__device__ float g_xz   [(size_t)NROWS*512];
__device__ float g_ut   [2ull*Bsz*DI*Lseq];
__device__ float g_dtraw[2ull*NROWS*8];
__device__ float g_bc   [2ull*NROWS*128];
__device__ float g_dtt  [2ull*Bsz*DI*Lseq];
__device__ float g_y    [2ull*NROWS*DI];

__device__ __forceinline__ float siluf(float v) { return v / (1.f + __expf(-v)); }
__device__ __forceinline__ float ex2f(float x) {
    float r; asm("ex2.approx.ftz.f32 %0, %1;" : "=f"(r) : "f"(x)); return r;
}

// ---------------- 1. LayerNorm ----------------
__global__ void ln_kernel(const float* __restrict__ x, const float* __restrict__ w,
                          const float* __restrict__ b) {
    int row  = blockIdx.x * 8 + (threadIdx.x >> 5);
    int lane = threadIdx.x & 31;
    float4 v = *(const float4*)(x + (size_t)row*DM + lane*4);
    float s  = v.x + v.y + v.z + v.w;
    float ss = v.x*v.x + v.y*v.y + v.z*v.z + v.w*v.w;
    #pragma unroll
    for (int o = 16; o; o >>= 1) {
        s  += __shfl_xor_sync(0xffffffffu, s,  o);
        ss += __shfl_xor_sync(0xffffffffu, ss, o);
    }
    float mu  = s * (1.f/128.f);
    float rs  = rsqrtf(ss * (1.f/128.f) - mu*mu + 1e-5f);
    float4 wv = *(const float4*)(w + lane*4);
    float4 bv = *(const float4*)(b + lane*4);
    float4 o4;
    o4.x = (v.x-mu)*rs*wv.x + bv.x;
    o4.y = (v.y-mu)*rs*wv.y + bv.y;
    o4.z = (v.z-mu)*rs*wv.z + bv.z;
    o4.w = (v.w-mu)*rs*wv.w + bv.w;
    *(float4*)(g_xn + (size_t)row*DM + lane*4) = o4;
}

// ---------------- 2. in_proj GEMM: M=16384,N=512,K=128, 128x64 tiles ----------------
__global__ void gemm_inproj(const float* __restrict__ W) {
    __shared__ __align__(16) float As[16][132];
    __shared__ __align__(16) float Bs[16][68];
    int tid = threadIdx.x;
    int bm0 = blockIdx.y * 128, bn0 = blockIdx.x * 64;
    int ar = tid >> 1, ac = (tid & 1) * 8;
    int brw = tid >> 2, bc = (tid & 3) * 4;
    int ty = tid >> 4, tx = tid & 15;
    float acc[8][4] = {};
    for (int k0 = 0; k0 < 128; k0 += 16) {
        float4 a0 = *(const float4*)(g_xn + (size_t)(bm0+ar)*DM + k0 + ac);
        float4 a1 = *(const float4*)(g_xn + (size_t)(bm0+ar)*DM + k0 + ac + 4);
        As[ac+0][ar]=a0.x; As[ac+1][ar]=a0.y; As[ac+2][ar]=a0.z; As[ac+3][ar]=a0.w;
        As[ac+4][ar]=a1.x; As[ac+5][ar]=a1.y; As[ac+6][ar]=a1.z; As[ac+7][ar]=a1.w;
        float4 wv = *(const float4*)(W + (size_t)(bn0+brw)*DM + k0 + bc);
        Bs[bc+0][brw]=wv.x; Bs[bc+1][brw]=wv.y; Bs[bc+2][brw]=wv.z; Bs[bc+3][brw]=wv.w;
        __syncthreads();
        #pragma unroll
        for (int kk = 0; kk < 16; kk++) {
            float4 x0 = *(float4*)&As[kk][ty*8];
            float4 x1 = *(float4*)&As[kk][ty*8+4];
            float4 bb = *(float4*)&Bs[kk][tx*4];
            float am[8] = {x0.x,x0.y,x0.z,x0.w,x1.x,x1.y,x1.z,x1.w};
            float bn[4] = {bb.x,bb.y,bb.z,bb.w};
            #pragma unroll
            for (int i=0;i<8;i++)
                #pragma unroll
                for (int j=0;j<4;j++) acc[i][j] += am[i]*bn[j];
        }
        __syncthreads();
    }
    #pragma unroll
    for (int i=0;i<8;i++) {
        float4 o4 = make_float4(acc[i][0],acc[i][1],acc[i][2],acc[i][3]);
        *(float4*)(g_xz + (size_t)(bm0+ty*8+i)*512 + bn0 + tx*4) = o4;
    }
}

// ---------------- 3. conv + silu (both dirs), u transposed ----------------
__global__ void conv_kernel(const float* __restrict__ cwF, const float* __restrict__ cbF,
                            const float* __restrict__ cwB, const float* __restrict__ cbB) {
    int c  = blockIdx.x * 128 + threadIdx.x;
    int t0 = blockIdx.y * 128;
    int bz = blockIdx.z; int b = bz >> 1; int br = bz & 1;
    const float* w4 = (br ? cwB : cwF) + c*4;
    float w0=w4[0], w1=w4[1], w2=w4[2], w3=w4[3];
    float bias = (br ? cbB : cbF)[c];
    const float* xzb = g_xz + (size_t)b*Lseq*512 + c;
    float* uo = g_ut + (((size_t)br*Bsz + b)*DI + c)*Lseq + t0;
    float r0, r1, r2;
    if (!br) {
        r0 = (t0-3 >= 0) ? xzb[(size_t)(t0-3)*512] : 0.f;
        r1 = (t0-2 >= 0) ? xzb[(size_t)(t0-2)*512] : 0.f;
        r2 = (t0-1 >= 0) ? xzb[(size_t)(t0-1)*512] : 0.f;
        #pragma unroll 4
        for (int i = 0; i < 128; i++) {
            float r3 = xzb[(size_t)(t0+i)*512];
            uo[i] = siluf(r0*w0 + r1*w1 + r2*w2 + r3*w3 + bias);
            r0 = r1; r1 = r2; r2 = r3;
        }
    } else {
        r0 = (t0 >= 3) ? xzb[(size_t)(Lseq+2-t0)*512] : 0.f;
        r1 = (t0 >= 2) ? xzb[(size_t)(Lseq+1-t0)*512] : 0.f;
        r2 = (t0 >= 1) ? xzb[(size_t)(Lseq  -t0)*512] : 0.f;
        #pragma unroll 4
        for (int i = 0; i < 128; i++) {
            float r3 = xzb[(size_t)(Lseq-1-(t0+i))*512];
            uo[i] = siluf(r0*w0 + r1*w1 + r2*w2 + r3*w3 + bias);
            r0 = r1; r1 = r2; r2 = r3;
        }
    }
}

// ---------------- 4. x_proj GEMM: M=16384,N=104,K=256, padded-split store ----------------
// bc row layout (128 floats): B state s at 8*(s/6)+s%6 ; C state s at 64+8*(s/6)+s%6
__global__ void gemm_xproj(const float* __restrict__ WF, const float* __restrict__ WB) {
    __shared__ __align__(16) float As[16][132];
    __shared__ __align__(16) float Bs[16][68];
    int brz = blockIdx.z;
    const float* W = brz ? WB : WF;
    int tid = threadIdx.x;
    int bn0 = blockIdx.x * 64, bm0 = blockIdx.y * 128;
    int b = bm0 >> 11, l0 = bm0 & 2047;
    int kr = tid >> 4, m4 = (tid & 15) * 4;
    int wr = tid >> 2, wc = (tid & 3) * 4;
    int ty = tid >> 4, tx = tid & 15;
    const float* Abase = g_ut + (((size_t)brz*Bsz + b)*DI) * Lseq + l0;
    float acc[8][4] = {};
    for (int k0 = 0; k0 < 256; k0 += 16) {
        *(float4*)&As[kr][m4]    = *(const float4*)(Abase + (size_t)(k0+kr)*Lseq + m4);
        *(float4*)&As[kr][m4+64] = *(const float4*)(Abase + (size_t)(k0+kr)*Lseq + m4 + 64);
        int n = bn0 + wr;
        float4 bv = make_float4(0.f,0.f,0.f,0.f);
        if (n < 104) bv = *(const float4*)(W + (size_t)n*256 + k0 + wc);
        Bs[wc+0][wr]=bv.x; Bs[wc+1][wr]=bv.y; Bs[wc+2][wr]=bv.z; Bs[wc+3][wr]=bv.w;
        __syncthreads();
        #pragma unroll
        for (int kk = 0; kk < 16; kk++) {
            float4 x0 = *(float4*)&As[kk][ty*8];
            float4 x1 = *(float4*)&As[kk][ty*8+4];
            float4 bb = *(float4*)&Bs[kk][tx*4];
            float am[8] = {x0.x,x0.y,x0.z,x0.w,x1.x,x1.y,x1.z,x1.w};
            float bn[4] = {bb.x,bb.y,bb.z,bb.w};
            #pragma unroll
            for (int i=0;i<8;i++)
                #pragma unroll
                for (int j=0;j<4;j++) acc[i][j] += am[i]*bn[j];
        }
        __syncthreads();
    }
    float* draw = g_dtraw + (size_t)brz*NROWS*8;
    float* bcp  = g_bc    + (size_t)brz*NROWS*128;
    #pragma unroll
    for (int i=0;i<8;i++) {
        size_t row = (size_t)(bm0 + ty*8 + i);
        #pragma unroll
        for (int j=0;j<4;j++) {
            int n = bn0 + tx*4 + j;
            if (n < 8) {
                draw[row*8 + n] = acc[i][j];
            } else if (n < 56) {
                int s = n - 8;
                bcp[row*128 + (s/6)*8 + s%6] = acc[i][j];
            } else if (n < 104) {
                int s = n - 56;
                bcp[row*128 + 64 + (s/6)*8 + s%6] = acc[i][j];
            }
        }
    }
}

// ---------------- 5. dt_proj + softplus (coalesced) ----------------
__global__ void dtproj_kernel(const float* __restrict__ dwF, const float* __restrict__ dbF,
                              const float* __restrict__ dwB, const float* __restrict__ dbB) {
    __shared__ float ws[64][9];
    int tid = threadIdx.x;
    int l  = blockIdx.x * 256 + tid;
    int d0 = blockIdx.y * 64;
    int br = blockIdx.z >> 3, b = blockIdx.z & 7;
    const float* dw = br ? dwB : dwF;
    const float* db = br ? dbB : dbF;
    for (int i = tid; i < 512; i += 256) ws[i>>3][i&7] = dw[(d0 + (i>>3))*8 + (i&7)];
    if (tid < 64) ws[tid][8] = db[d0 + tid];
    __syncthreads();
    const float* xr = g_dtraw + (size_t)br*NROWS*8 + ((size_t)b*Lseq + l)*8;
    float4 x0 = *(const float4*)xr;
    float4 x1 = *(const float4*)(xr + 4);
    float xv[8] = {x0.x,x0.y,x0.z,x0.w,x1.x,x1.y,x1.z,x1.w};
    float* outp = g_dtt + (((size_t)br*Bsz + b)*DI + d0)*Lseq + l;
    for (int d = 0; d < 64; d++) {
        float acc = ws[d][8];
        #pragma unroll
        for (int r = 0; r < 8; r++) acc += xv[r] * ws[d][r];
        float sp = (acc > 15.f) ? acc : log1pf(__expf(acc));
        outp[(size_t)d*Lseq] = sp;
    }
}

// ---------------- 6. selective scan: warp = 4 d's, lane group of 8, 6 states/lane ----------------
__global__ void __launch_bounds__(64) scan_kernel(
        const float* __restrict__ AlogF, const float* __restrict__ DpF,
        const float* __restrict__ AlogB, const float* __restrict__ DpB) {
    int warp = threadIdx.x >> 5, lane = threadIdx.x & 31;
    int wq = blockIdx.x * 2 + warp;        // 0..63 : which quad of d's
    int b  = blockIdx.y, br = blockIdx.z;
    int g = lane >> 3, sub = lane & 7;
    int d = wq * 4 + g;
    const float* Alog = br ? AlogB : AlogF;
    const float* Dpv  = br ? DpB  : DpF;
    const float L2E = 1.44269504f;
    float A[6];
    #pragma unroll
    for (int k = 0; k < 6; k++) A[k] = -__expf(Alog[d*DS + 6*sub + k]) * L2E;
    float Dpd = Dpv[d];
    const float* dtp = g_dtt + (((size_t)br*Bsz + b)*DI + d)*Lseq;
    const float* up  = g_ut  + (((size_t)br*Bsz + b)*DI + d)*Lseq;
    const float* xd  = g_bc + ((size_t)br*NROWS + (size_t)b*Lseq)*128 + 8*sub;
    float* yo = g_y + ((size_t)br*NROWS + (size_t)b*Lseq)*DI + d;

    float h[6] = {};
    float4 dt4 = *(const float4*)dtp;
    float4 u4  = *(const float4*)up;
    float4 Bv[4][2], Cv[4][2];
    #pragma unroll
    for (int i = 0; i < 4; i++) {
        const float* xr = xd + (size_t)i*128;
        Bv[i][0] = *(const float4*)(xr);
        Bv[i][1] = *(const float4*)(xr + 4);
        Cv[i][0] = *(const float4*)(xr + 64);
        Cv[i][1] = *(const float4*)(xr + 68);
    }
    for (int t0 = 0; t0 < Lseq; t0 += 4) {
        int tn = (t0 + 4 < Lseq) ? (t0 + 4) : t0;
        float4 dt4n = *(const float4*)(dtp + tn);
        float4 u4n  = *(const float4*)(up + tn);
        float4 Bn[4][2], Cn[4][2];
        #pragma unroll
        for (int i = 0; i < 4; i++) {
            const float* xr = xd + (size_t)(tn + i)*128;
            Bn[i][0] = *(const float4*)(xr);
            Bn[i][1] = *(const float4*)(xr + 4);
            Cn[i][0] = *(const float4*)(xr + 64);
            Cn[i][1] = *(const float4*)(xr + 68);
        }
        float dts[4] = {dt4.x, dt4.y, dt4.z, dt4.w};
        float us [4] = {u4.x,  u4.y,  u4.z,  u4.w};
        #pragma unroll
        for (int i = 0; i < 4; i++) {
            float dtv = dts[i], uv = us[i];
            float du = dtv * uv;
            float4 bx = Bv[i][0], by = Bv[i][1];
            float4 cx = Cv[i][0], cy = Cv[i][1];
            h[0] = ex2f(dtv*A[0])*h[0] + du*bx.x;
            h[1] = ex2f(dtv*A[1])*h[1] + du*bx.y;
            h[2] = ex2f(dtv*A[2])*h[2] + du*bx.z;
            h[3] = ex2f(dtv*A[3])*h[3] + du*bx.w;
            h[4] = ex2f(dtv*A[4])*h[4] + du*by.x;
            h[5] = ex2f(dtv*A[5])*h[5] + du*by.y;
            float p = h[0]*cx.x + h[1]*cx.y + h[2]*cx.z + h[3]*cx.w
                    + h[4]*cy.x + h[5]*cy.y;
            p += __shfl_xor_sync(0xffffffffu, p, 4);
            p += __shfl_xor_sync(0xffffffffu, p, 2);
            p += __shfl_xor_sync(0xffffffffu, p, 1);
            if (sub == 0) {
                int t = t0 + i;
                int row = br ? (Lseq - 1 - t) : t;
                yo[(size_t)row*DI] = p + uv * Dpd;
            }
        }
        dt4 = dt4n; u4 = u4n;
        #pragma unroll
        for (int i = 0; i < 4; i++) {
            Bv[i][0]=Bn[i][0]; Bv[i][1]=Bn[i][1];
            Cv[i][0]=Cn[i][0]; Cv[i][1]=Cn[i][1];
        }
    }
}

// ---------------- 7. out_proj GEMM fused gate+residual: M=16384,N=128,K=256 ----------------
__global__ void gemm_out(const float* __restrict__ W, const float* __restrict__ x,
                         float* __restrict__ out) {
    __shared__ __align__(16) float As[16][132];
    __shared__ __align__(16) float Bs[16][68];
    int tid = threadIdx.x;
    int bm0 = blockIdx.y * 128, bn0 = blockIdx.x * 64;
    int ar = tid >> 1, ac = (tid & 1) * 8;
    int brw = tid >> 2, bc = (tid & 3) * 4;
    int ty = tid >> 4, tx = tid & 15;
    float acc[8][4] = {};
    for (int k0 = 0; k0 < 256; k0 += 16) {
        size_t m = (size_t)(bm0 + ar);
        #pragma unroll
        for (int h = 0; h < 2; h++) {
            size_t idx = m*DI + k0 + ac + h*4;
            float4 yf = *(const float4*)(g_y + idx);
            float4 yb = *(const float4*)(g_y + (size_t)NROWS*DI + idx);
            float4 zz = *(const float4*)(g_xz + m*512 + 256 + k0 + ac + h*4);
            As[ac+h*4+0][ar] = (yf.x + yb.x) * siluf(zz.x);
            As[ac+h*4+1][ar] = (yf.y + yb.y) * siluf(zz.y);
            As[ac+h*4+2][ar] = (yf.z + yb.z) * siluf(zz.z);
            As[ac+h*4+3][ar] = (yf.w + yb.w) * siluf(zz.w);
        }
        float4 wv = *(const float4*)(W + (size_t)(bn0+brw)*DI + k0 + bc);
        Bs[bc+0][brw]=wv.x; Bs[bc+1][brw]=wv.y; Bs[bc+2][brw]=wv.z; Bs[bc+3][brw]=wv.w;
        __syncthreads();
        #pragma unroll
        for (int kk = 0; kk < 16; kk++) {
            float4 x0 = *(float4*)&As[kk][ty*8];
            float4 x1 = *(float4*)&As[kk][ty*8+4];
            float4 bb = *(float4*)&Bs[kk][tx*4];
            float am[8] = {x0.x,x0.y,x0.z,x0.w,x1.x,x1.y,x1.z,x1.w};
            float bn[4] = {bb.x,bb.y,bb.z,bb.w};
            #pragma unroll
            for (int i=0;i<8;i++)
                #pragma unroll
                for (int j=0;j<4;j++) acc[i][j] += am[i]*bn[j];
        }
        __syncthreads();
    }
    #pragma unroll
    for (int i = 0; i < 8; i++) {
        size_t m = (size_t)(bm0 + ty*8 + i);
        float4 r = *(const float4*)(x + m*DM + bn0 + tx*4);
        float4 o4 = make_float4(acc[i][0]+r.x, acc[i][1]+r.y, acc[i][2]+r.z, acc[i][3]+r.w);
        *(float4*)(out + m*DM + bn0 + tx*4) = o4;
    }
}

extern "C" void kernel_launch(void* const* d_in, const int* in_sizes, int n_in,
                              void* d_out, int out_size) {
    const float* x        = (const float*)d_in[0];
    const float* ln_w     = (const float*)d_in[1];
    const float* ln_b     = (const float*)d_in[2];
    const float* in_w     = (const float*)d_in[3];
    const float* out_w    = (const float*)d_in[4];
    const float* conv_w   = (const float*)d_in[5];
    const float* conv_b   = (const float*)d_in[6];
    const float* xproj_w  = (const float*)d_in[7];
    const float* dt_w     = (const float*)d_in[8];
    const float* dt_b     = (const float*)d_in[9];
    const float* A_log    = (const float*)d_in[10];
    const float* Dp       = (const float*)d_in[11];
    const float* conv_wb  = (const float*)d_in[12];
    const float* conv_bb  = (const float*)d_in[13];
    const float* xproj_wb = (const float*)d_in[14];
    const float* dt_wb    = (const float*)d_in[15];
    const float* dt_bb    = (const float*)d_in[16];
    const float* A_logb   = (const float*)d_in[17];
    const float* Dpb      = (const float*)d_in[18];
    float* out = (float*)d_out;

    ln_kernel<<<NROWS/8, 256>>>(x, ln_w, ln_b);
    gemm_inproj<<<dim3(8, 128), 256>>>(in_w);
    conv_kernel<<<dim3(2, 16, 16), 128>>>(conv_w, conv_b, conv_wb, conv_bb);
    gemm_xproj<<<dim3(2, 128, 2), 256>>>(xproj_w, xproj_wb);
    dtproj_kernel<<<dim3(8, 4, 16), 256>>>(dt_w, dt_b, dt_wb, dt_bb);
    scan_kernel<<<dim3(32, 8, 2), 64>>>(A_log, Dp, A_logb, Dpb);
    gemm_out<<<dim3(2, 128), 256>>>(out_w, x, out);
}